// round 10
// baseline (speedup 1.0000x reference)
#include <cuda_runtime.h>
#include <cstdint>

#define B_DIM    8
#define C_OUT    64
#define NK       7
#define GROUP_IN 4
#define C_IN     1792              // 64*4*7
#define L_DIM    4096
#define TILE     256
#define HALO     16                // covers |shift| <= 15
#define ROWW     (TILE + 2*HALO)   // 288 floats per staged row
#define ROWB     (ROWW * 4)        // 1152 bytes per staged row
#define NCH      (GROUP_IN * NK)   // 28 channels per c_out
#define THREADS  256
#define GRID     304               // 2 persistent CTAs per GB300 SM
#define NTILES   (B_DIM * C_OUT * (L_DIM / TILE))   // 8192
#define BUFSZ    (NCH * ROWW)      // 8064 floats per buffer
#define BUFB     (BUFSZ * 4)       // 32256 bytes per buffer

// --- TMA bulk 1D: global -> shared, mbarrier transaction-counted ---
__device__ __forceinline__ void bulk_g2s(uint32_t dst, const void* src,
                                         unsigned bytes, uint32_t mbar) {
    asm volatile(
        "cp.async.bulk.shared::cluster.global.mbarrier::complete_tx::bytes "
        "[%0], [%1], %2, [%3];"
        :: "r"(dst), "l"(src), "r"(bytes), "r"(mbar) : "memory");
}
__device__ __forceinline__ void mbar_init(uint32_t mbar, unsigned cnt) {
    asm volatile("mbarrier.init.shared.b64 [%0], %1;" :: "r"(mbar), "r"(cnt) : "memory");
}
__device__ __forceinline__ void mbar_arrive_expect(uint32_t mbar, unsigned bytes) {
    asm volatile("mbarrier.arrive.expect_tx.shared.b64 _, [%0], %1;"
                 :: "r"(mbar), "r"(bytes) : "memory");
}
__device__ __forceinline__ void mbar_arrive(uint32_t mbar) {
    asm volatile("mbarrier.arrive.shared.b64 _, [%0];" :: "r"(mbar) : "memory");
}
__device__ __forceinline__ void mbar_wait(uint32_t mbar, unsigned ph) {
    asm volatile(
        "{\n\t.reg .pred P;\n\t"
        "LAB_%=:\n\t"
        "mbarrier.try_wait.parity.acquire.cta.shared::cta.b64 P, [%0], %1, 0x989680;\n\t"
        "@P bra.uni DONE_%=;\n\t"
        "bra.uni LAB_%=;\n\t"
        "DONE_%=:\n\t}"
        :: "r"(mbar), "r"(ph) : "memory");
}

__global__ __launch_bounds__(THREADS, 2) void addshift_kernel(
    const float* __restrict__ x,
    const int*   __restrict__ si1,
    const int*   __restrict__ si2,
    const int*   __restrict__ si3,
    float*       __restrict__ out)
{
    extern __shared__ float sm[];                 // [3][NCH][ROWW]
    __shared__ unsigned tab[C_OUT * NCH];         // packed per-(co,lc) offsets
    __shared__ __align__(8) unsigned long long mbar_s[6];  // tmb0..2, cmb0..2

    const int tid = threadIdx.x;
    const uint32_t sm_base = (uint32_t)__cvta_generic_to_shared(sm);
    const uint32_t tmb0 = (uint32_t)__cvta_generic_to_shared(&mbar_s[0]);
    const uint32_t tmb1 = (uint32_t)__cvta_generic_to_shared(&mbar_s[1]);
    const uint32_t tmb2 = (uint32_t)__cvta_generic_to_shared(&mbar_s[2]);
    const uint32_t cmb0 = (uint32_t)__cvta_generic_to_shared(&mbar_s[3]);
    const uint32_t cmb1 = (uint32_t)__cvta_generic_to_shared(&mbar_s[4]);
    const uint32_t cmb2 = (uint32_t)__cvta_generic_to_shared(&mbar_s[5]);

    // ---- one-time offset table: in-row byte offset = (1 + 5*(idx%7))*4 ----
    for (int c = tid; c < C_IN; c += THREADS) {
        int g  = c / (C_OUT * NK);
        int r  = c - g * (C_OUT * NK);
        int co = r / NK;
        int k  = r - co * NK;
        int lc = g * NK + k;
        unsigned o1 = 4u + 20u * (unsigned)(si1[c] % NK);
        unsigned o2 = 4u + 20u * (unsigned)(si2[c] % NK);
        unsigned o3 = 4u + 20u * (unsigned)(si3[c] % NK);
        tab[co * NCH + lc] = o1 | (o2 << 8) | (o3 << 16);
    }
    if (tid == 0) {
        mbar_init(tmb0, 32); mbar_init(tmb1, 32); mbar_init(tmb2, 32);
        mbar_init(cmb0, THREADS); mbar_init(cmb1, THREADS); mbar_init(cmb2, THREADS);
    }
    // per-lane staged-row constant (meaningful for tid < 28)
    const int crel = ((tid / NK) * (C_OUT * NK) + tid % NK) * L_DIM;
    __syncthreads();   // tables + mbarrier init visible; last bar.sync in kernel

    const size_t OSZ = (size_t)B_DIM * C_OUT * L_DIM;   // one output tensor

    // ---- stage one tile into a slot (CALL ONLY FROM WARP 0) ----
    auto stage = [&](int w, uint32_t smslot, uint32_t mb) {
        const int b   = w >> 10;
        const int rem = w & 1023;
        const int co  = rem >> 4;
        const int tx  = rem & 15;
        const bool front = (tx == 0);
        const bool back  = (tx == 15);
        // zero the 16-float OOB halo (bytes disjoint from the bulk copy)
        if (front | back) {
            uint32_t zb = smslot + (front ? 0u : (unsigned)((TILE + HALO) * 4));
            for (int i = tid; i < NCH * 4; i += 32) {          // 112 float4 chunks
                uint32_t a = zb + (unsigned)(i >> 2) * ROWB + (unsigned)(i & 3) * 16u;
                asm volatile("st.shared.v4.b32 [%0], {%1,%1,%1,%1};"
                             :: "r"(a), "r"(0) : "memory");
            }
        }
        const unsigned sz = (front | back) ? (ROWB - 64u) : (unsigned)ROWB;
        // all 32 lanes arrive (releases the STS zeros); lane 0 adds expect_tx
        if (tid == 0) mbar_arrive_expect(mb, NCH * sz);
        else          mbar_arrive(mb);
        if (tid < NCH) {
            const int gstart = (tx << 8) - HALO;
            const float* src = x + ((size_t)b * C_IN + (size_t)co * NK) * L_DIM
                             + crel + gstart + (front ? HALO : 0);
            bulk_g2s(smslot + (uint32_t)tid * ROWB + (front ? 64u : 0u), src, sz, mb);
        }
    };

    // ---- accumulate one tile from a slot; thread owns t = t0 + tid ----
    auto accum = [&](int w, int slot) {
        const int b   = w >> 10;
        const int rem = w & 1023;
        const int co  = rem >> 4;
        const int tx  = rem & 15;
        const unsigned* tabco = tab + co * NCH;
        const char* smb = (const char*)(sm + slot * BUFSZ)
                        + (size_t)((unsigned)tid * 4u);
        float a1 = 0.f, a2 = 0.f, a3 = 0.f;
        #pragma unroll
        for (int lc = 0; lc < NCH; ++lc) {
            unsigned p = tabco[lc];                    // one LDS.32 broadcast
            a1 += *(const float*)(smb + (p & 255u)        + lc * ROWB);
            a2 += *(const float*)(smb + ((p >> 8) & 255u) + lc * ROWB);
            a3 += *(const float*)(smb + (p >> 16)         + lc * ROWB);
        }
        const size_t ob = ((size_t)b * C_OUT + co) * L_DIM + (tx << 8) + tid;
        out[ob]           = a1;
        out[ob + OSZ]     = a2;
        out[ob + 2 * OSZ] = a3;
    };

    // ---- prologue: stage two tiles ahead ----
    int w = blockIdx.x;
    if (tid < 32) {
        stage(w, sm_base, tmb0);
        if (w + GRID < NTILES) stage(w + GRID, sm_base + BUFB, tmb1);
    }

    unsigned t0 = 0, t1 = 0, t2 = 0, c0 = 0, c1 = 0, c2 = 0;
    bool first2 = true;

    while (true) {
        // ===== consume slot 0 (tile w); stage w+2G -> slot 2 =====
        int ws = w + 2 * GRID;
        if (ws < NTILES && tid < 32) {
            if (!first2) { mbar_wait(cmb2, c2); c2 ^= 1; }
            stage(ws, sm_base + 2 * BUFB, tmb2);
        }
        first2 = false;
        mbar_wait(tmb0, t0); t0 ^= 1;
        accum(w, 0);
        mbar_arrive(cmb0);
        w += GRID; if (w >= NTILES) break;

        // ===== consume slot 1; stage w+2G -> slot 0 =====
        ws = w + 2 * GRID;
        if (ws < NTILES && tid < 32) {
            mbar_wait(cmb0, c0); c0 ^= 1;
            stage(ws, sm_base, tmb0);
        }
        mbar_wait(tmb1, t1); t1 ^= 1;
        accum(w, 1);
        mbar_arrive(cmb1);
        w += GRID; if (w >= NTILES) break;

        // ===== consume slot 2; stage w+2G -> slot 1 =====
        ws = w + 2 * GRID;
        if (ws < NTILES && tid < 32) {
            mbar_wait(cmb1, c1); c1 ^= 1;
            stage(ws, sm_base + BUFB, tmb1);
        }
        mbar_wait(tmb2, t2); t2 ^= 1;
        accum(w, 2);
        mbar_arrive(cmb2);
        w += GRID; if (w >= NTILES) break;
    }
}

extern "C" void kernel_launch(void* const* d_in, const int* in_sizes, int n_in,
                              void* d_out, int out_size) {
    const float* x   = (const float*)d_in[0];
    const int*   si1 = (const int*)d_in[1];
    const int*   si2 = (const int*)d_in[2];
    const int*   si3 = (const int*)d_in[3];
    float* out = (float*)d_out;

    const int smem_bytes = 3 * BUFB;          // 96768
    cudaFuncSetAttribute(addshift_kernel,
                         cudaFuncAttributeMaxDynamicSharedMemorySize, smem_bytes);

    addshift_kernel<<<GRID, THREADS, smem_bytes>>>(x, si1, si2, si3, out);
}

// round 11
// speedup vs baseline: 1.0974x; 1.0974x over previous
#include <cuda_runtime.h>
#include <cstdint>

#define B_DIM    8
#define C_OUT    64
#define NK       7
#define GROUP_IN 4
#define C_IN     1792              // 64*4*7
#define L_DIM    4096
#define TILE     256
#define HALO     16                // covers |shift| <= 15
#define ROWW     (TILE + 2*HALO)   // 288 floats per staged row
#define ROWB     (ROWW * 4)        // 1152 bytes per staged row
#define NCH      (GROUP_IN * NK)   // 28 channels per c_out
#define HROWS    14                // rows per half-buffer
#define HBUFB    (HROWS * ROWB)    // 16128 bytes per half-buffer
#define RING     3
#define THREADS  256
#define CTAS_SM  4
#define GRID     (152 * CTAS_SM)   // 608 persistent CTAs
#define NTILES   (B_DIM * C_OUT * (L_DIM / TILE))   // 8192

// --- TMA bulk 1D: global -> shared, mbarrier transaction-counted ---
__device__ __forceinline__ void bulk_g2s(uint32_t dst, const void* src,
                                         unsigned bytes, uint32_t mbar) {
    asm volatile(
        "cp.async.bulk.shared::cluster.global.mbarrier::complete_tx::bytes "
        "[%0], [%1], %2, [%3];"
        :: "r"(dst), "l"(src), "r"(bytes), "r"(mbar) : "memory");
}
__device__ __forceinline__ void mbar_init(uint32_t mbar, unsigned cnt) {
    asm volatile("mbarrier.init.shared.b64 [%0], %1;" :: "r"(mbar), "r"(cnt) : "memory");
}
__device__ __forceinline__ void mbar_arrive_expect(uint32_t mbar, unsigned bytes) {
    asm volatile("mbarrier.arrive.expect_tx.shared.b64 _, [%0], %1;"
                 :: "r"(mbar), "r"(bytes) : "memory");
}
__device__ __forceinline__ void mbar_arrive(uint32_t mbar) {
    asm volatile("mbarrier.arrive.shared.b64 _, [%0];" :: "r"(mbar) : "memory");
}
__device__ __forceinline__ void mbar_wait(uint32_t mbar, unsigned ph) {
    asm volatile(
        "{\n\t.reg .pred P;\n\t"
        "LAB_%=:\n\t"
        "mbarrier.try_wait.parity.acquire.cta.shared::cta.b64 P, [%0], %1, 0x989680;\n\t"
        "@P bra.uni DONE_%=;\n\t"
        "bra.uni LAB_%=;\n\t"
        "DONE_%=:\n\t}"
        :: "r"(mbar), "r"(ph) : "memory");
}

__global__ __launch_bounds__(THREADS, CTAS_SM) void addshift_kernel(
    const float* __restrict__ x,
    const int*   __restrict__ si1,
    const int*   __restrict__ si2,
    const int*   __restrict__ si3,
    float*       __restrict__ out)
{
    extern __shared__ float sm[];                 // ring of 3 half-buffers
    __shared__ unsigned tab[C_OUT * NCH];         // packed per-(co,lc) offsets
    __shared__ int crel_s[NCH];                   // channel elem-offset per local row
    __shared__ __align__(8) unsigned long long mbar_s[2 * RING]; // tmb[3], cmb[3]

    const int tid = threadIdx.x;
    const uint32_t sm_base  = (uint32_t)__cvta_generic_to_shared(sm);
    const uint32_t tmb_base = (uint32_t)__cvta_generic_to_shared(&mbar_s[0]);
    const uint32_t cmb_base = (uint32_t)__cvta_generic_to_shared(&mbar_s[RING]);

    // ---- one-time tables ----
    if (tid < NCH)
        crel_s[tid] = ((tid / NK) * (C_OUT * NK) + tid % NK) * L_DIM;
    for (int c = tid; c < C_IN; c += THREADS) {
        int g  = c / (C_OUT * NK);
        int r  = c - g * (C_OUT * NK);
        int co = r / NK;
        int k  = r - co * NK;
        int lc = g * NK + k;
        unsigned o1 = 4u + 20u * (unsigned)(si1[c] % NK);
        unsigned o2 = 4u + 20u * (unsigned)(si2[c] % NK);
        unsigned o3 = 4u + 20u * (unsigned)(si3[c] % NK);
        tab[co * NCH + lc] = o1 | (o2 << 8) | (o3 << 16);
    }
    if (tid == 0) {
        #pragma unroll
        for (int s = 0; s < RING; ++s) {
            mbar_init(tmb_base + 8u * s, 32);        // warp-0 lanes
            mbar_init(cmb_base + 8u * s, THREADS);   // all consumers
        }
    }
    __syncthreads();   // tables + mbarrier init visible; last bar.sync in kernel

    const size_t OSZ = (size_t)B_DIM * C_OUT * L_DIM;   // one output tensor

    // ---- stage one HALF-tile (14 rows) into ring slot s (warp 0 only) ----
    auto stage = [&](int w, int part, unsigned s) {
        const int b   = w >> 10;
        const int rem = w & 1023;
        const int co  = rem >> 4;
        const int tx  = rem & 15;
        const bool front = (tx == 0);
        const bool back  = (tx == 15);
        const uint32_t slotb = sm_base + s * (unsigned)HBUFB;
        // zero the 16-float OOB halo (bytes disjoint from the bulk copy)
        if (front | back) {
            uint32_t zb = slotb + (front ? 0u : (unsigned)((TILE + HALO) * 4));
            for (int i = tid; i < HROWS * 4; i += 32) {        // 56 float4 chunks
                uint32_t a = zb + (unsigned)(i >> 2) * ROWB + (unsigned)(i & 3) * 16u;
                asm volatile("st.shared.v4.b32 [%0], {%1,%1,%1,%1};"
                             :: "r"(a), "r"(0) : "memory");
            }
        }
        const unsigned sz = (front | back) ? (ROWB - 64u) : (unsigned)ROWB;
        if (tid == 0) mbar_arrive_expect(tmb_base + 8u * s, HROWS * sz);
        else          mbar_arrive(tmb_base + 8u * s);
        if (tid < HROWS) {
            const int lc = part * HROWS + tid;
            const int gstart = (tx << 8) - HALO;
            const float* src = x + ((size_t)b * C_IN + (size_t)co * NK) * L_DIM
                             + crel_s[lc] + gstart + (front ? HALO : 0);
            bulk_g2s(slotb + (uint32_t)tid * ROWB + (front ? 64u : 0u), src, sz,
                     tmb_base + 8u * s);
        }
    };

    // ---- accumulate 14 channels of half (co,part) from slot s ----
    auto accum_half = [&](int co, int part, unsigned s,
                          float& a1, float& a2, float& a3) {
        const unsigned* tabp = tab + co * NCH + part * HROWS;
        const char* smb = (const char*)sm + s * (unsigned)HBUFB
                        + (size_t)((unsigned)tid * 4u);
        #pragma unroll
        for (int j = 0; j < HROWS; ++j) {
            unsigned p = tabp[j];                     // one LDS.32 broadcast
            a1 += *(const float*)(smb + (p & 255u)        + j * ROWB);
            a2 += *(const float*)(smb + ((p >> 8) & 255u) + j * ROWB);
            a3 += *(const float*)(smb + (p >> 16)         + j * ROWB);
        }
    };

    // ---- prologue: stage both halves of first tile into slots 0,1 ----
    int w = blockIdx.x;
    if (w < NTILES && tid < 32) { stage(w, 0, 0); stage(w, 1, 1); }

    unsigned s = 0;            // slot of current tile's first half
    unsigned tbits = 0, cbits = 0;
    bool first = true;

    while (w < NTILES) {
        const int wn = w + GRID;
        unsigned s1 = s + 1;  if (s1 == RING) s1 = 0;
        unsigned s2 = s1 + 1; if (s2 == RING) s2 = 0;

        // stage next tile's part 0 into s2
        if (wn < NTILES && tid < 32) {
            if (!first) { mbar_wait(cmb_base + 8u * s2, (cbits >> s2) & 1u); cbits ^= 1u << s2; }
            stage(wn, 0, s2);
        }
        first = false;

        const int b   = w >> 10;
        const int rem = w & 1023;
        const int co  = rem >> 4;
        const int tx  = rem & 15;

        // consume part 0 from s
        mbar_wait(tmb_base + 8u * s, (tbits >> s) & 1u); tbits ^= 1u << s;
        float a1 = 0.f, a2 = 0.f, a3 = 0.f;
        accum_half(co, 0, s, a1, a2, a3);
        mbar_arrive(cmb_base + 8u * s);

        // stage next tile's part 1 into s (freed once all 256 arrive)
        if (wn < NTILES && tid < 32) {
            mbar_wait(cmb_base + 8u * s, (cbits >> s) & 1u); cbits ^= 1u << s;
            stage(wn, 1, s);
        }

        // consume part 1 from s1, then store
        mbar_wait(tmb_base + 8u * s1, (tbits >> s1) & 1u); tbits ^= 1u << s1;
        accum_half(co, 1, s1, a1, a2, a3);
        const size_t ob = ((size_t)b * C_OUT + co) * L_DIM + (tx << 8) + tid;
        out[ob]           = a1;
        out[ob + OSZ]     = a2;
        out[ob + 2 * OSZ] = a3;
        mbar_arrive(cmb_base + 8u * s1);

        w = wn;
        s = s2;
    }
}

extern "C" void kernel_launch(void* const* d_in, const int* in_sizes, int n_in,
                              void* d_out, int out_size) {
    const float* x   = (const float*)d_in[0];
    const int*   si1 = (const int*)d_in[1];
    const int*   si2 = (const int*)d_in[2];
    const int*   si3 = (const int*)d_in[3];
    float* out = (float*)d_out;

    const int smem_bytes = RING * HBUFB;      // 48384
    cudaFuncSetAttribute(addshift_kernel,
                         cudaFuncAttributeMaxDynamicSharedMemorySize, smem_bytes);

    addshift_kernel<<<GRID, THREADS, smem_bytes>>>(x, si1, si2, si3, out);
}

// round 12
// speedup vs baseline: 1.1444x; 1.0428x over previous
#include <cuda_runtime.h>
#include <cstdint>

#define B_DIM    8
#define C_OUT    64
#define NK       7
#define GROUP_IN 4
#define C_IN     1792              // 64*4*7
#define L_DIM    4096
#define TILE     512
#define HALO     16                // covers |shift| <= 15
#define ROWW     (TILE + 2*HALO)   // 544 floats per staged row
#define ROWB     (ROWW * 4)        // 2176 bytes per staged row
#define NCH      (GROUP_IN * NK)   // 28 channels per c_out
#define HROWS    14                // rows per half-buffer
#define HBUFB    (HROWS * ROWB)    // 30464 bytes per half-buffer
#define THREADS  256
#define CTAS_SM  3
#define GRID     (152 * CTAS_SM)   // 456 persistent CTAs
#define NTILES   (B_DIM * C_OUT * (L_DIM / TILE))   // 4096

// --- TMA bulk 1D: global -> shared, mbarrier transaction-counted ---
__device__ __forceinline__ void bulk_g2s(uint32_t dst, const void* src,
                                         unsigned bytes, uint32_t mbar) {
    asm volatile(
        "cp.async.bulk.shared::cluster.global.mbarrier::complete_tx::bytes "
        "[%0], [%1], %2, [%3];"
        :: "r"(dst), "l"(src), "r"(bytes), "r"(mbar) : "memory");
}
__device__ __forceinline__ void mbar_init(uint32_t mbar, unsigned cnt) {
    asm volatile("mbarrier.init.shared.b64 [%0], %1;" :: "r"(mbar), "r"(cnt) : "memory");
}
__device__ __forceinline__ void mbar_arrive_expect(uint32_t mbar, unsigned bytes) {
    asm volatile("mbarrier.arrive.expect_tx.shared.b64 _, [%0], %1;"
                 :: "r"(mbar), "r"(bytes) : "memory");
}
__device__ __forceinline__ void mbar_arrive(uint32_t mbar) {
    asm volatile("mbarrier.arrive.shared.b64 _, [%0];" :: "r"(mbar) : "memory");
}
__device__ __forceinline__ void mbar_wait(uint32_t mbar, unsigned ph) {
    asm volatile(
        "{\n\t.reg .pred P;\n\t"
        "LAB_%=:\n\t"
        "mbarrier.try_wait.parity.acquire.cta.shared::cta.b64 P, [%0], %1, 0x989680;\n\t"
        "@P bra.uni DONE_%=;\n\t"
        "bra.uni LAB_%=;\n\t"
        "DONE_%=:\n\t}"
        :: "r"(mbar), "r"(ph) : "memory");
}

__global__ __launch_bounds__(THREADS, CTAS_SM) void addshift_kernel(
    const float* __restrict__ x,
    const int*   __restrict__ si1,
    const int*   __restrict__ si2,
    const int*   __restrict__ si3,
    float*       __restrict__ out)
{
    extern __shared__ float sm[];                 // 2 half-buffers (slot0, slot1)
    __shared__ unsigned tab[C_OUT * NCH];         // packed per-(co,lc) offsets
    __shared__ int crel_s[NCH];                   // channel elem-offset per local row
    __shared__ __align__(8) unsigned long long mbar_s[4];  // tmb0 tmb1 cmb0 cmb1

    const int tid = threadIdx.x;
    const uint32_t sm_base = (uint32_t)__cvta_generic_to_shared(sm);
    const uint32_t tmb0 = (uint32_t)__cvta_generic_to_shared(&mbar_s[0]);
    const uint32_t tmb1 = (uint32_t)__cvta_generic_to_shared(&mbar_s[1]);
    const uint32_t cmb0 = (uint32_t)__cvta_generic_to_shared(&mbar_s[2]);
    const uint32_t cmb1 = (uint32_t)__cvta_generic_to_shared(&mbar_s[3]);

    // ---- one-time tables ----
    if (tid < NCH)
        crel_s[tid] = ((tid / NK) * (C_OUT * NK) + tid % NK) * L_DIM;
    for (int c = tid; c < C_IN; c += THREADS) {
        int g  = c / (C_OUT * NK);
        int r  = c - g * (C_OUT * NK);
        int co = r / NK;
        int k  = r - co * NK;
        int lc = g * NK + k;
        unsigned o1 = 4u + 20u * (unsigned)(si1[c] % NK);
        unsigned o2 = 4u + 20u * (unsigned)(si2[c] % NK);
        unsigned o3 = 4u + 20u * (unsigned)(si3[c] % NK);
        tab[co * NCH + lc] = o1 | (o2 << 8) | (o3 << 16);
    }
    if (tid == 0) {
        mbar_init(tmb0, 32); mbar_init(tmb1, 32);      // warp-0 lanes
        mbar_init(cmb0, THREADS); mbar_init(cmb1, THREADS);
    }
    __syncthreads();   // tables + mbarrier init visible; last bar.sync in kernel

    const unsigned OSZ = (unsigned)B_DIM * C_OUT * L_DIM;   // one output tensor

    // ---- stage one HALF-tile (14 rows) into slot (warp 0 only) ----
    auto stage = [&](int w, int part, uint32_t slotb, uint32_t tmb) {
        const int b   = w >> 9;                 // 512 tiles per batch
        const int rem = w & 511;
        const int co  = rem >> 3;
        const int tx  = rem & 7;
        const bool front = (tx == 0);
        const bool back  = (tx == 7);
        // zero the 16-float OOB halo (bytes disjoint from the bulk copy)
        if (front | back) {
            uint32_t zb = slotb + (front ? 0u : (unsigned)((TILE + HALO) * 4));
            for (int i = tid; i < HROWS * 4; i += 32) {     // 56 float4 chunks
                uint32_t a = zb + (unsigned)(i >> 2) * ROWB + (unsigned)(i & 3) * 16u;
                asm volatile("st.shared.v4.b32 [%0], {%1,%1,%1,%1};"
                             :: "r"(a), "r"(0) : "memory");
            }
        }
        const unsigned sz = (front | back) ? (ROWB - 64u) : (unsigned)ROWB;
        if (tid == 0) mbar_arrive_expect(tmb, HROWS * sz);
        else          mbar_arrive(tmb);
        if (tid < HROWS) {
            const int gstart = (tx << 9) - HALO;
            const float* src = x + ((size_t)b * C_IN + (size_t)co * NK) * L_DIM
                             + crel_s[part * HROWS + tid] + gstart
                             + (front ? HALO : 0);
            bulk_g2s(slotb + (uint32_t)tid * ROWB + (front ? 64u : 0u), src, sz, tmb);
        }
    };

    // ---- accumulate 14 channels x 2 points from a half-buffer ----
    // smb = slot base + tid*4; point0 = t0+tid, point1 = t0+tid+256 (+1024 B,
    // folded into the LDS immediate -> second point costs only LDS+FADD).
    auto accum = [&](int co, int part, const char* smb, float* a) {
        const unsigned* tp = tab + co * NCH + part * HROWS;
        #pragma unroll
        for (int j = 0; j < HROWS; ++j) {
            unsigned p = tp[j];                       // one LDS.32 broadcast
            const char* r0 = smb + j * ROWB;
            unsigned e1 = p & 255u;
            unsigned e2 = (p >> 8) & 255u;
            unsigned e3 = p >> 16;
            a[0] += *(const float*)(r0 + e1);
            a[1] += *(const float*)(r0 + e1 + 1024);
            a[2] += *(const float*)(r0 + e2);
            a[3] += *(const float*)(r0 + e2 + 1024);
            a[4] += *(const float*)(r0 + e3);
            a[5] += *(const float*)(r0 + e3 + 1024);
        }
    };

    // ---- prologue: stage part 0 of first tile into slot 0 ----
    int w = blockIdx.x;
    if (w < NTILES && tid < 32) stage(w, 0, sm_base, tmb0);

    unsigned tp0 = 0, tp1 = 0, cp0 = 0, cp1 = 0;
    bool first = true;

    while (w < NTILES) {
        const int b   = w >> 9;
        const int rem = w & 511;
        const int co  = rem >> 3;
        const int tx  = rem & 7;
        const int wn  = w + GRID;

        // stage part 1 of this tile into slot 1 (free once prev tile's part1 drained)
        if (tid < 32) {
            if (!first) { mbar_wait(cmb1, cp1); cp1 ^= 1; }
            stage(w, 1, sm_base + HBUFB, tmb1);
        }
        first = false;

        float a[6] = {0.f, 0.f, 0.f, 0.f, 0.f, 0.f};

        // consume part 0 from slot 0
        mbar_wait(tmb0, tp0); tp0 ^= 1;
        accum(co, 0, (const char*)sm + (unsigned)tid * 4u, a);
        mbar_arrive(cmb0);

        // stage next tile's part 0 into slot 0 (free once all drained part 0)
        if (wn < NTILES && tid < 32) {
            mbar_wait(cmb0, cp0); cp0 ^= 1;
            stage(wn, 0, sm_base, tmb0);
        }

        // consume part 1 from slot 1, then store both points x 3 outputs
        mbar_wait(tmb1, tp1); tp1 ^= 1;
        accum(co, 1, (const char*)sm + HBUFB + (unsigned)tid * 4u, a);

        const unsigned ob = ((unsigned)(b * C_OUT + co)) * L_DIM + (tx << 9) + tid;
        out[ob]                 = a[0];
        out[ob + 256]           = a[1];
        out[ob + OSZ]           = a[2];
        out[ob + OSZ + 256]     = a[3];
        out[ob + 2 * OSZ]       = a[4];
        out[ob + 2 * OSZ + 256] = a[5];
        mbar_arrive(cmb1);

        w = wn;
    }
}

extern "C" void kernel_launch(void* const* d_in, const int* in_sizes, int n_in,
                              void* d_out, int out_size) {
    const float* x   = (const float*)d_in[0];
    const int*   si1 = (const int*)d_in[1];
    const int*   si2 = (const int*)d_in[2];
    const int*   si3 = (const int*)d_in[3];
    float* out = (float*)d_out;

    const int smem_bytes = 2 * HBUFB;         // 60928
    cudaFuncSetAttribute(addshift_kernel,
                         cudaFuncAttributeMaxDynamicSharedMemorySize, smem_bytes);

    addshift_kernel<<<GRID, THREADS, smem_bytes>>>(x, si1, si2, si3, out);
}